// round 1
// baseline (speedup 1.0000x reference)
#include <cuda_runtime.h>
#include <cuda_bf16.h>

// ---------------------------------------------------------------------------
// HT model: MLP (64->128->64->32->32) per (b,j), leaf contraction, 5 tree
// levels of (pairwise product -> batched GEMM), top projection to Y=1000.
//
// Single templated fp32 tiled-GEMM kernel drives everything:
//   C[j][m,n] = act( sum_k Aop[j][m,k] * W[j][n/k] + bias[n] )
// where Aop is either A1 rows or elementwise product A1*A2 (tree levels),
// and W is either (K,N) row-major (MLP layout) or (N,K) row-major (P tensors).
// ---------------------------------------------------------------------------

#define BM 128
#define BN 64
#define BK 16

// Scratch (no cudaMalloc allowed). Sizes:
//  g_h1  : 262144 x 128 fp32 (h1; reused as h3)
//  g_bufA: 262144 x  64 fp32 (h2; then tree ping)
//  g_bufB: 262144 x  64 fp32 (F;  then tree pong)
__device__ float g_h1[262144L * 128];
__device__ float g_bufA[262144L * 64];
__device__ float g_bufB[262144L * 64];

template <bool PROD, bool WT, bool RELU>
__global__ void __launch_bounds__(256) gemm_k(
    const float* __restrict__ A1base, long ldA, long jStrideA, int aOff2,
    const float* __restrict__ Wbase, long jStrideW,
    const float* __restrict__ bias,
    float* __restrict__ Cbase, long ldC, long jStrideC,
    int Mdim, int Ndim, int Kdim)
{
    const int j = blockIdx.z;
    const float* A1 = A1base + (long)j * jStrideA;
    const float* W  = Wbase  + (long)j * jStrideW;
    float* C        = Cbase  + (long)j * jStrideC;

    const int m0 = blockIdx.x * BM;
    const int n0 = blockIdx.y * BN;
    const int tid = threadIdx.x;
    const int tx = tid & 15;   // 0..15 -> 4 output cols each
    const int ty = tid >> 4;   // 0..15 -> 8 output rows each

    __shared__ float As[BK][BM];
    __shared__ float Bs[BK][BN];

    float acc[8][4];
#pragma unroll
    for (int i = 0; i < 8; i++)
#pragma unroll
        for (int jj = 0; jj < 4; jj++) acc[i][jj] = 0.f;

    // A-load mapping: 128 rows x 16 k, 256 threads -> 2 x float4 each
    const int ar = tid >> 2;        // 0..63 (rows ar and ar+64)
    const int ak = (tid & 3) * 4;   // 0,4,8,12
    // B-load mapping (WT: weights are (N,K) row-major)
    const int bn_wt = tid & 63;           // col (g)
    const int bk_wt = (tid >> 6) * 4;     // k group
    // B-load mapping (non-WT: weights are (K,N) row-major)
    const int bk_nt = tid >> 4;           // 0..15, one k each
    const int bn_nt = (tid & 15) * 4;     // col group

    for (int kt = 0; kt < Kdim; kt += BK) {
        // ---- load A tile (optionally fused pair-product) ----
        const float* pa = A1 + (long)(m0 + ar) * ldA + kt + ak;
#pragma unroll
        for (int h = 0; h < 2; h++) {
            const float* p = pa + (long)h * 64 * ldA;
            float4 v = *(const float4*)p;
            if (PROD) {
                float4 w = *(const float4*)(p + aOff2);
                v.x *= w.x; v.y *= w.y; v.z *= w.z; v.w *= w.w;
            }
            const int r = ar + h * 64;
            As[ak + 0][r] = v.x;
            As[ak + 1][r] = v.y;
            As[ak + 2][r] = v.z;
            As[ak + 3][r] = v.w;
        }
        // ---- load B tile ----
        if (WT) {
            float4 v = make_float4(0.f, 0.f, 0.f, 0.f);
            if (n0 + bn_wt < Ndim)
                v = *(const float4*)(W + (long)(n0 + bn_wt) * Kdim + kt + bk_wt);
            Bs[bk_wt + 0][bn_wt] = v.x;
            Bs[bk_wt + 1][bn_wt] = v.y;
            Bs[bk_wt + 2][bn_wt] = v.z;
            Bs[bk_wt + 3][bn_wt] = v.w;
        } else {
            float4 v = make_float4(0.f, 0.f, 0.f, 0.f);
            if (n0 + bn_nt < Ndim)
                v = *(const float4*)(W + (long)(kt + bk_nt) * Ndim + n0 + bn_nt);
            *(float4*)&Bs[bk_nt][bn_nt] = v;
        }
        __syncthreads();

        // ---- MACs ----
#pragma unroll
        for (int k = 0; k < BK; k++) {
            float4 a0 = *(const float4*)&As[k][ty * 8];
            float4 a1 = *(const float4*)&As[k][ty * 8 + 4];
            float4 b  = *(const float4*)&Bs[k][tx * 4];
            float av[8] = {a0.x, a0.y, a0.z, a0.w, a1.x, a1.y, a1.z, a1.w};
            float bv[4] = {b.x, b.y, b.z, b.w};
#pragma unroll
            for (int i = 0; i < 8; i++)
#pragma unroll
                for (int jj = 0; jj < 4; jj++)
                    acc[i][jj] = fmaf(av[i], bv[jj], acc[i][jj]);
        }
        __syncthreads();
    }

    // ---- epilogue ----
#pragma unroll
    for (int i = 0; i < 8; i++) {
        const long m = m0 + ty * 8 + i;   // Mdim is always a multiple of 128
        float* crow = C + m * ldC;
#pragma unroll
        for (int jj = 0; jj < 4; jj++) {
            const int n = n0 + tx * 4 + jj;
            if (n < Ndim) {
                float v = acc[i][jj];
                if (bias) v += __ldg(&bias[n]);
                if (RELU) v = fmaxf(v, 0.f);
                crow[n] = v;
            }
        }
    }
}

extern "C" void kernel_launch(void* const* d_in, const int* in_sizes, int n_in,
                              void* d_out, int out_size)
{
    const float* X    = (const float*)d_in[0];   // (4096,64,64)
    const float* W1   = (const float*)d_in[1];   // (64,128)
    const float* b1   = (const float*)d_in[2];
    const float* W2   = (const float*)d_in[3];   // (128,64)
    const float* b2   = (const float*)d_in[4];
    const float* W3   = (const float*)d_in[5];   // (64,32)
    const float* b3   = (const float*)d_in[6];
    const float* W4   = (const float*)d_in[7];   // (32,32)
    const float* b4   = (const float*)d_in[8];
    const float* P0   = (const float*)d_in[9];   // (64,64,32)
    const float* P1   = (const float*)d_in[10];  // (32,128,64)
    const float* P2   = (const float*)d_in[11];  // (16,256,128)
    const float* P3   = (const float*)d_in[12];  // (8,512,256)
    const float* P4   = (const float*)d_in[13];  // (4,512,512)
    const float* P5   = (const float*)d_in[14];  // (2,512,512)
    const float* Ptop = (const float*)d_in[15];  // (1000,512)
    float* out = (float*)d_out;                  // (4096,1000)

    float *h1, *bufA, *bufB;
    cudaGetSymbolAddress((void**)&h1,  g_h1);
    cudaGetSymbolAddress((void**)&bufA, g_bufA);
    cudaGetSymbolAddress((void**)&bufB, g_bufB);

    const dim3 blk(256);
    const int BR = 262144;  // B*N rows through the MLP

    // MLP layer 1: (262144,64) @ (64,128) + b1, relu -> h1
    gemm_k<false, false, true><<<dim3(2048, 2, 1), blk>>>(
        X, 64, 0, 0, W1, 0, b1, h1, 128, 0, BR, 128, 64);
    // MLP layer 2: -> bufA (h2, 64)
    gemm_k<false, false, true><<<dim3(2048, 1, 1), blk>>>(
        h1, 128, 0, 0, W2, 0, b2, bufA, 64, 0, BR, 64, 128);
    // MLP layer 3: -> h1 (h3, 32)
    gemm_k<false, false, true><<<dim3(2048, 1, 1), blk>>>(
        bufA, 64, 0, 0, W3, 0, b3, h1, 32, 0, BR, 32, 64);
    // MLP layer 4 (no relu): -> bufB (F, 32)
    gemm_k<false, false, false><<<dim3(2048, 1, 1), blk>>>(
        h1, 32, 0, 0, W4, 0, b4, bufB, 32, 0, BR, 32, 32);

    // Leaf: t0[b,j,a] = sum_m P0[j,a,m] * F[b,j,m]   -> bufA (B,64,64)
    gemm_k<false, true, false><<<dim3(32, 1, 64), blk>>>(
        bufB, 2048, 32, 0, P0, 2048, nullptr, bufA, 4096, 64, 4096, 64, 32);

    // Level 1: in bufA (B,64,64) -> out bufB (B,32,128)
    gemm_k<true, true, false><<<dim3(32, 2, 32), blk>>>(
        bufA, 4096, 128, 64, P1, 128L * 64, nullptr, bufB, 4096, 128, 4096, 128, 64);
    // Level 2: bufB (B,32,128) -> bufA (B,16,256)
    gemm_k<true, true, false><<<dim3(32, 4, 16), blk>>>(
        bufB, 4096, 256, 128, P2, 256L * 128, nullptr, bufA, 4096, 256, 4096, 256, 128);
    // Level 3: bufA (B,16,256) -> bufB (B,8,512)
    gemm_k<true, true, false><<<dim3(32, 8, 8), blk>>>(
        bufA, 4096, 512, 256, P3, 512L * 256, nullptr, bufB, 4096, 512, 4096, 512, 256);
    // Level 4: bufB (B,8,512) -> bufA (B,4,512)
    gemm_k<true, true, false><<<dim3(32, 8, 4), blk>>>(
        bufB, 4096, 1024, 512, P4, 512L * 512, nullptr, bufA, 2048, 512, 4096, 512, 512);
    // Level 5: bufA (B,4,512) -> bufB (B,2,512)
    gemm_k<true, true, false><<<dim3(32, 8, 2), blk>>>(
        bufA, 2048, 1024, 512, P5, 512L * 512, nullptr, bufB, 1024, 512, 4096, 512, 512);

    // Top: out[b,y] = sum_a Ptop[y,a] * (t5[b,0,a]*t5[b,1,a])
    gemm_k<true, true, false><<<dim3(32, 16, 1), blk>>>(
        bufB, 1024, 0, 512, Ptop, 0, nullptr, out, 1000, 0, 4096, 1000, 512);
}

// round 5
// speedup vs baseline: 1.6493x; 1.6493x over previous
#include <cuda_runtime.h>
#include <cstdint>

// ---------------------------------------------------------------------------
// HT model via split-tf32 mma.sync (baseline-PTX tensor path; tcgen05 is
// rejected by the harness's compute_103 virtual target).
//   C[j][m,n] = act( sum_k Aop[j][m,k] * W[j][n,k or k,n] + bias[n] )
// Aop = A1 rows or fused pair-product A1*A1[+aOff2] (tree levels).
// fp32 operands split x = hi + lo (hi = cvt.rna.tf32, lo = residual);
// 3 MMAs per product (hi*hi + hi*lo + lo*hi) into fp32 accumulators
// -> ~2^-21 relative error per GEMM, far under the 1e-3 budget.
// CTA tile 128x64, BK=16, 8 warps (4x2), warp tile 32x32 of m16n8k8.
// SINGLE smem buffer (30720 B < 48 KB default cap -- no cudaFuncSetAttribute
// needed, which is what broke Round 4) with register-staged pipelining:
// next-stage gmem loads are issued before this stage's MMAs.
// ---------------------------------------------------------------------------

__device__ float g_h1[262144L * 128];
__device__ float g_bufA[262144L * 64];
__device__ float g_bufB[262144L * 64];

#define LDS_PAD 20
// layout (floats): Ahi[128*20]=2560 | Alo 2560 | Bhi[64*20]=1280 | Blo 1280
#define BUF_FLOATS 7680
#define DYN_SMEM (BUF_FLOATS * 4)   // 30720 bytes

static __device__ __forceinline__ float tf32_hi(float x) {
    uint32_t h;
    asm("cvt.rna.tf32.f32 %0, %1;" : "=r"(h) : "f"(x));
    return __uint_as_float(h);
}

#define MMA_TF32(d, a, b)                                                     \
    asm volatile(                                                             \
        "mma.sync.aligned.m16n8k8.row.col.f32.tf32.tf32.f32 "                 \
        "{%0,%1,%2,%3}, {%4,%5,%6,%7}, {%8,%9}, {%0,%1,%2,%3};"               \
        : "+f"((d)[0]), "+f"((d)[1]), "+f"((d)[2]), "+f"((d)[3])              \
        : "r"((a)[0]), "r"((a)[1]), "r"((a)[2]), "r"((a)[3]),                 \
          "r"((b)[0]), "r"((b)[1]))

template <bool PROD, bool WT, bool RELU>
__global__ void __launch_bounds__(256) mma_gemm(
    const float* __restrict__ A1base, long ldA, long jStrideA, int aOff2,
    const float* __restrict__ Wbase, long jStrideW,
    const float* __restrict__ bias,
    float* __restrict__ Cbase, long ldC, long jStrideC,
    int Ndim, int Kdim)
{
    extern __shared__ float sm[];

    const int j = blockIdx.z;
    const float* A1 = A1base + (long)j * jStrideA;
    const float* W  = Wbase  + (long)j * jStrideW;
    float* C        = Cbase  + (long)j * jStrideC;
    const int m0 = blockIdx.x * 128;
    const int n0 = blockIdx.y * 64;

    const int tid = threadIdx.x;
    const int wid = tid >> 5, lid = tid & 31;
    const int wm = wid >> 1, wn = wid & 1;     // warps: 4 along M x 2 along N
    const int g = lid >> 2, tig = lid & 3;

    const int arow = tid >> 1;          // 0..127
    const int akb  = (tid & 1) * 8;     // 0 or 8
    const int brow = arow & 63;         // 0..63
    const bool bldr = tid < 128;

    float d[2][4][4];
#pragma unroll
    for (int mt = 0; mt < 2; mt++)
#pragma unroll
        for (int nt = 0; nt < 4; nt++)
#pragma unroll
            for (int q = 0; q < 4; q++) d[mt][nt][q] = 0.f;

    const int nst = Kdim >> 4;
    float4 av[2], bv[2];

    auto load_stage = [&](int s) {
        const float* pa = A1 + (long)(m0 + arow) * ldA + s * 16 + akb;
#pragma unroll
        for (int h = 0; h < 2; h++) {
            float4 v = *(const float4*)(pa + h * 4);
            if (PROD) {
                float4 u = *(const float4*)(pa + aOff2 + h * 4);
                v.x *= u.x; v.y *= u.y; v.z *= u.z; v.w *= u.w;
            }
            av[h] = v;
        }
        if (bldr) {
            const bool valid = (n0 + brow) < Ndim;
#pragma unroll
            for (int h = 0; h < 2; h++) {
                float4 v = make_float4(0.f, 0.f, 0.f, 0.f);
                if (valid) {
                    if (WT) {
                        v = *(const float4*)(W + (long)(n0 + brow) * Kdim + s * 16 + akb + h * 4);
                    } else {
                        const float* pw = W + (long)(s * 16 + akb + h * 4) * Ndim + n0 + brow;
                        v.x = pw[0]; v.y = pw[(long)Ndim];
                        v.z = pw[2 * (long)Ndim]; v.w = pw[3 * (long)Ndim];
                    }
                }
                bv[h] = v;
            }
        }
    };
    auto store_stage = [&]() {
#pragma unroll
        for (int h = 0; h < 2; h++) {
            float4 v = av[h], hi, lo;
            hi.x = tf32_hi(v.x); lo.x = v.x - hi.x;
            hi.y = tf32_hi(v.y); lo.y = v.y - hi.y;
            hi.z = tf32_hi(v.z); lo.z = v.z - hi.z;
            hi.w = tf32_hi(v.w); lo.w = v.w - hi.w;
            const int off = arow * LDS_PAD + akb + h * 4;
            *(float4*)(sm + off)        = hi;
            *(float4*)(sm + 2560 + off) = lo;
        }
        if (bldr) {
#pragma unroll
            for (int h = 0; h < 2; h++) {
                float4 v = bv[h], hi, lo;
                hi.x = tf32_hi(v.x); lo.x = v.x - hi.x;
                hi.y = tf32_hi(v.y); lo.y = v.y - hi.y;
                hi.z = tf32_hi(v.z); lo.z = v.z - hi.z;
                hi.w = tf32_hi(v.w); lo.w = v.w - hi.w;
                const int off = brow * LDS_PAD + akb + h * 4;
                *(float4*)(sm + 5120 + off) = hi;
                *(float4*)(sm + 6400 + off) = lo;
            }
        }
    };

    load_stage(0);

    for (int s = 0; s < nst; s++) {
        store_stage();
        __syncthreads();
        if (s + 1 < nst) load_stage(s + 1);   // overlaps with compute below

        const float* Ahi = sm;
        const float* Alo = sm + 2560;
        const float* Bhi = sm + 5120;
        const float* Blo = sm + 6400;

#pragma unroll
        for (int kc = 0; kc < 2; kc++) {
            const int col = kc * 8 + tig;
            uint32_t ah[2][4], al[2][4], bh[4][2], bl[4][2];
#pragma unroll
            for (int mt = 0; mt < 2; mt++) {
                const int r = wm * 32 + mt * 16 + g;
                ah[mt][0] = __float_as_uint(Ahi[r * LDS_PAD + col]);
                ah[mt][1] = __float_as_uint(Ahi[(r + 8) * LDS_PAD + col]);
                ah[mt][2] = __float_as_uint(Ahi[r * LDS_PAD + col + 4]);
                ah[mt][3] = __float_as_uint(Ahi[(r + 8) * LDS_PAD + col + 4]);
                al[mt][0] = __float_as_uint(Alo[r * LDS_PAD + col]);
                al[mt][1] = __float_as_uint(Alo[(r + 8) * LDS_PAD + col]);
                al[mt][2] = __float_as_uint(Alo[r * LDS_PAD + col + 4]);
                al[mt][3] = __float_as_uint(Alo[(r + 8) * LDS_PAD + col + 4]);
            }
#pragma unroll
            for (int nt = 0; nt < 4; nt++) {
                const int n = wn * 32 + nt * 8 + g;
                bh[nt][0] = __float_as_uint(Bhi[n * LDS_PAD + col]);
                bh[nt][1] = __float_as_uint(Bhi[n * LDS_PAD + col + 4]);
                bl[nt][0] = __float_as_uint(Blo[n * LDS_PAD + col]);
                bl[nt][1] = __float_as_uint(Blo[n * LDS_PAD + col + 4]);
            }
#pragma unroll
            for (int mt = 0; mt < 2; mt++)
#pragma unroll
                for (int nt = 0; nt < 4; nt++) {
                    MMA_TF32(d[mt][nt], ah[mt], bh[nt]);
                    MMA_TF32(d[mt][nt], ah[mt], bl[nt]);
                    MMA_TF32(d[mt][nt], al[mt], bh[nt]);
                }
        }
        __syncthreads();   // smem consumed; safe to overwrite next iteration
    }

    // ---- epilogue ----
#pragma unroll
    for (int mt = 0; mt < 2; mt++) {
        const int r0 = m0 + wm * 32 + mt * 16 + g;
#pragma unroll
        for (int nt = 0; nt < 4; nt++) {
            const int c = n0 + wn * 32 + nt * 8 + 2 * tig;
#pragma unroll
            for (int half = 0; half < 2; half++) {
                const long row = r0 + half * 8;
                float v0 = d[mt][nt][half * 2 + 0];
                float v1 = d[mt][nt][half * 2 + 1];
                if (c < Ndim) {
                    if (bias) v0 += __ldg(&bias[c]);
                    if (RELU) v0 = fmaxf(v0, 0.f);
                    C[row * ldC + c] = v0;
                }
                if (c + 1 < Ndim) {
                    if (bias) v1 += __ldg(&bias[c + 1]);
                    if (RELU) v1 = fmaxf(v1, 0.f);
                    C[row * ldC + c + 1] = v1;
                }
            }
        }
    }
}

extern "C" void kernel_launch(void* const* d_in, const int* in_sizes, int n_in,
                              void* d_out, int out_size)
{
    const float* X    = (const float*)d_in[0];   // (4096,64,64)
    const float* W1   = (const float*)d_in[1];   // (64,128)
    const float* b1   = (const float*)d_in[2];
    const float* W2   = (const float*)d_in[3];   // (128,64)
    const float* b2   = (const float*)d_in[4];
    const float* W3   = (const float*)d_in[5];   // (64,32)
    const float* b3   = (const float*)d_in[6];
    const float* W4   = (const float*)d_in[7];   // (32,32)
    const float* b4   = (const float*)d_in[8];
    const float* P0   = (const float*)d_in[9];   // (64,64,32)
    const float* P1   = (const float*)d_in[10];  // (32,128,64)
    const float* P2   = (const float*)d_in[11];  // (16,256,128)
    const float* P3   = (const float*)d_in[12];  // (8,512,256)
    const float* P4   = (const float*)d_in[13];  // (4,512,512)
    const float* P5   = (const float*)d_in[14];  // (2,512,512)
    const float* Ptop = (const float*)d_in[15];  // (1000,512)
    float* out = (float*)d_out;                  // (4096,1000)

    float *h1, *bufA, *bufB;
    cudaGetSymbolAddress((void**)&h1,  g_h1);
    cudaGetSymbolAddress((void**)&bufA, g_bufA);
    cudaGetSymbolAddress((void**)&bufB, g_bufB);

    const dim3 blk(256);

    // MLP over 262144 rows
    mma_gemm<false, false, true><<<dim3(2048, 2, 1), blk, DYN_SMEM>>>(
        X, 64, 0, 0, W1, 0, b1, h1, 128, 0, 128, 64);
    mma_gemm<false, false, true><<<dim3(2048, 1, 1), blk, DYN_SMEM>>>(
        h1, 128, 0, 0, W2, 0, b2, bufA, 64, 0, 64, 128);
    mma_gemm<false, false, true><<<dim3(2048, 1, 1), blk, DYN_SMEM>>>(
        bufA, 64, 0, 0, W3, 0, b3, h1, 32, 0, 32, 64);
    mma_gemm<false, false, false><<<dim3(2048, 1, 1), blk, DYN_SMEM>>>(
        h1, 32, 0, 0, W4, 0, b4, bufB, 32, 0, 32, 32);

    // Leaf: t0[b,j,a] = sum_m P0[j,a,m] * F[b,j,m]   -> bufA (B,64,64)
    mma_gemm<false, true, false><<<dim3(32, 1, 64), blk, DYN_SMEM>>>(
        bufB, 2048, 32, 0, P0, 2048, nullptr, bufA, 4096, 64, 64, 32);

    // Tree levels (pair-product fused into A load)
    mma_gemm<true, true, false><<<dim3(32, 2, 32), blk, DYN_SMEM>>>(
        bufA, 4096, 128, 64, P1, 128L * 64, nullptr, bufB, 4096, 128, 128, 64);
    mma_gemm<true, true, false><<<dim3(32, 4, 16), blk, DYN_SMEM>>>(
        bufB, 4096, 256, 128, P2, 256L * 128, nullptr, bufA, 4096, 256, 256, 128);
    mma_gemm<true, true, false><<<dim3(32, 8, 8), blk, DYN_SMEM>>>(
        bufA, 4096, 512, 256, P3, 512L * 256, nullptr, bufB, 4096, 512, 512, 256);
    mma_gemm<true, true, false><<<dim3(32, 8, 4), blk, DYN_SMEM>>>(
        bufB, 4096, 1024, 512, P4, 512L * 512, nullptr, bufA, 2048, 512, 512, 512);
    mma_gemm<true, true, false><<<dim3(32, 8, 2), blk, DYN_SMEM>>>(
        bufA, 2048, 1024, 512, P5, 512L * 512, nullptr, bufB, 1024, 512, 512, 512);

    // Top: out[b,y] = sum_a Ptop[y,a] * (t5[b,0,a]*t5[b,1,a])
    mma_gemm<true, true, false><<<dim3(32, 16, 1), blk, DYN_SMEM>>>(
        bufB, 1024, 0, 512, Ptop, 0, nullptr, out, 1000, 0, 1000, 512);
}

// round 6
// speedup vs baseline: 1.9547x; 1.1852x over previous
#include <cuda_runtime.h>
#include <cstdint>

// ---------------------------------------------------------------------------
// HT model via split-tf32 mma.sync, cp.async double-buffered pipeline.
//   C[j][m,n] = act( sum_k Aop[j][m,k] * W[j][n,k or k,n] + bias[n] )
// Aop = A1 rows or fused pair-product A1*A1[+aOff2] (tree levels).
// smem holds RAW fp32 tiles (cp.async 16B/4B, XOR-swizzled, conflict-free);
// the tf32 split x = hi + lo happens in registers at fragment load, then
// 3 MMAs per product (hi*hi + hi*lo + lo*hi) into fp32 accumulators.
// CTA tile 128x64, BK=16, 8 warps (4x2), warp tile 32x32 of m16n8k8.
// Two cp.async stages: PROD 2x20480B, else 2x12288B -- under 48KB cap.
// ---------------------------------------------------------------------------

__device__ float g_h1[262144L * 128];
__device__ float g_bufA[262144L * 64];
__device__ float g_bufB[262144L * 64];

static __device__ __forceinline__ uint32_t smem_u32(const void* p) {
    uint32_t a;
    asm("{ .reg .u64 t; cvta.to.shared.u64 t, %1; cvt.u32.u64 %0, t; }" : "=r"(a) : "l"(p));
    return a;
}
static __device__ __forceinline__ void cp16(uint32_t dst, const void* src) {
    asm volatile("cp.async.ca.shared.global [%0], [%1], 16;" :: "r"(dst), "l"(src));
}
static __device__ __forceinline__ void cp4(uint32_t dst, const void* src) {
    asm volatile("cp.async.ca.shared.global [%0], [%1], 4;" :: "r"(dst), "l"(src));
}
#define CP_COMMIT() asm volatile("cp.async.commit_group;" ::: "memory")
#define CP_WAIT1()  asm volatile("cp.async.wait_group 1;" ::: "memory")

static __device__ __forceinline__ float tf32_hi(float x) {
    uint32_t h;
    asm("cvt.rna.tf32.f32 %0, %1;" : "=r"(h) : "f"(x));
    return __uint_as_float(h);
}

#define MMA_TF32(d, a, b)                                                     \
    asm volatile(                                                             \
        "mma.sync.aligned.m16n8k8.row.col.f32.tf32.tf32.f32 "                 \
        "{%0,%1,%2,%3}, {%4,%5,%6,%7}, {%8,%9}, {%0,%1,%2,%3};"               \
        : "+f"((d)[0]), "+f"((d)[1]), "+f"((d)[2]), "+f"((d)[3])              \
        : "r"((a)[0]), "r"((a)[1]), "r"((a)[2]), "r"((a)[3]),                 \
          "r"((b)[0]), "r"((b)[1]))

// swizzled float-index of element (row, k) inside a [rows x 16] tile
static __device__ __forceinline__ int swz(int row, int k) {
    return row * 16 + ((((k >> 2) ^ ((row >> 1) & 3))) << 2) + (k & 3);
}

template <bool PROD, bool WT, bool RELU>
__global__ void __launch_bounds__(256, 3) mma_gemm(
    const float* __restrict__ A1base, long ldA, long jStrideA, int aOff2,
    const float* __restrict__ Wbase, long jStrideW,
    const float* __restrict__ bias,
    float* __restrict__ Cbase, long ldC, long jStrideC,
    int Ndim, int Kdim)
{
    extern __shared__ float sm[];
    // stage layout (floats): A[2048] | (PROD: Aodd[2048]) | B[1024]
    constexpr int BOFF = PROD ? 4096 : 2048;
    constexpr int STG  = PROD ? 5120 : 3072;

    const int j = blockIdx.z;
    const float* A1 = A1base + (long)j * jStrideA;
    const float* W  = Wbase  + (long)j * jStrideW;
    float* C        = Cbase  + (long)j * jStrideC;
    const int m0 = blockIdx.x * 128;
    const int n0 = blockIdx.y * 64;

    const int tid = threadIdx.x;
    const int wid = tid >> 5, lid = tid & 31;
    const int wm = wid >> 1, wn = wid & 1;     // warps: 4 along M x 2 along N
    const int g = lid >> 2, tig = lid & 3;

    const uint32_t smb = smem_u32(sm);

    float d[2][4][4];
#pragma unroll
    for (int mt = 0; mt < 2; mt++)
#pragma unroll
        for (int nt = 0; nt < 4; nt++)
#pragma unroll
            for (int q = 0; q < 4; q++) d[mt][nt][q] = 0.f;

    const int nst = Kdim >> 4;

    auto issue_stage = [&](int s, int buf) {
        const uint32_t sb = smb + (uint32_t)buf * (STG * 4);
        // A tile: 128 rows x 16 floats = 512 16B chunks, 2 per thread
#pragma unroll
        for (int q = 0; q < 2; q++) {
            const int cid = tid + q * 256;
            const int row = cid >> 2, c = cid & 3;
            const uint32_t dst = sb + (uint32_t)(row * 16 + ((c ^ ((row >> 1) & 3)) << 2)) * 4;
            const float* src = A1 + (long)(m0 + row) * ldA + s * 16 + c * 4;
            cp16(dst, src);
            if (PROD) cp16(dst + 2048 * 4, src + aOff2);
        }
        // B tile: 64 rows x 16 floats
        if (WT) {
            const int row = tid >> 2, c = tid & 3;
            const int n = (n0 + row < Ndim) ? (n0 + row) : (Ndim - 1);
            const uint32_t dst = sb + (uint32_t)(BOFF + row * 16 + ((c ^ ((row >> 1) & 3)) << 2)) * 4;
            cp16(dst, W + (long)n * Kdim + s * 16 + c * 4);
        } else {
#pragma unroll
            for (int i = 0; i < 4; i++) {
                const int e = tid * 4 + i;
                const int row = e >> 4, k = e & 15;
                const int n = (n0 + row < Ndim) ? (n0 + row) : (Ndim - 1);
                const uint32_t dst = sb + (uint32_t)(BOFF + swz(row, k)) * 4;
                cp4(dst, W + (long)(s * 16 + k) * Ndim + n);
            }
        }
    };

    auto compute = [&](int buf) {
        const float* As = sm + buf * STG;
        const float* Ao = As + 2048;
        const float* Bs = As + BOFF;
#pragma unroll
        for (int kc = 0; kc < 2; kc++) {
            uint32_t ah[2][4], al[2][4], bh[4][2], bl[4][2];
#pragma unroll
            for (int mt = 0; mt < 2; mt++) {
#pragma unroll
                for (int i = 0; i < 4; i++) {
                    const int r = wm * 32 + mt * 16 + g + (i & 1) * 8;
                    const int kk = kc * 8 + tig + (i >> 1) * 4;
                    const int idx = swz(r, kk);
                    float v = As[idx];
                    if (PROD) v *= Ao[idx];
                    const float hi = tf32_hi(v);
                    ah[mt][i] = __float_as_uint(hi);
                    al[mt][i] = __float_as_uint(v - hi);
                }
            }
#pragma unroll
            for (int nt = 0; nt < 4; nt++) {
#pragma unroll
                for (int i = 0; i < 2; i++) {
                    const int n = wn * 32 + nt * 8 + g;
                    const int kk = kc * 8 + tig + i * 4;
                    const int idx = swz(n, kk);
                    const float v = Bs[idx];
                    const float hi = tf32_hi(v);
                    bh[nt][i] = __float_as_uint(hi);
                    bl[nt][i] = __float_as_uint(v - hi);
                }
            }
#pragma unroll
            for (int mt = 0; mt < 2; mt++)
#pragma unroll
                for (int nt = 0; nt < 4; nt++) {
                    MMA_TF32(d[mt][nt], ah[mt], bh[nt]);
                    MMA_TF32(d[mt][nt], ah[mt], bl[nt]);
                    MMA_TF32(d[mt][nt], al[mt], bh[nt]);
                }
        }
    };

    // ---- pipeline: 2 cp.async stages in flight ----
    issue_stage(0, 0);
    CP_COMMIT();
    if (nst > 1) issue_stage(1, 1);
    CP_COMMIT();

    for (int s = 0; s < nst; s++) {
        CP_WAIT1();
        __syncthreads();
        compute(s & 1);
        __syncthreads();
        if (s + 2 < nst) issue_stage(s + 2, s & 1);
        CP_COMMIT();
    }

    // ---- epilogue ----
#pragma unroll
    for (int mt = 0; mt < 2; mt++) {
        const int r0 = m0 + wm * 32 + mt * 16 + g;
#pragma unroll
        for (int nt = 0; nt < 4; nt++) {
            const int c = n0 + wn * 32 + nt * 8 + 2 * tig;
#pragma unroll
            for (int half = 0; half < 2; half++) {
                const long row = r0 + half * 8;
                float v0 = d[mt][nt][half * 2 + 0];
                float v1 = d[mt][nt][half * 2 + 1];
                if (c < Ndim) {
                    if (bias) v0 += __ldg(&bias[c]);
                    if (RELU) v0 = fmaxf(v0, 0.f);
                    C[row * ldC + c] = v0;
                }
                if (c + 1 < Ndim) {
                    if (bias) v1 += __ldg(&bias[c + 1]);
                    if (RELU) v1 = fmaxf(v1, 0.f);
                    C[row * ldC + c + 1] = v1;
                }
            }
        }
    }
}

extern "C" void kernel_launch(void* const* d_in, const int* in_sizes, int n_in,
                              void* d_out, int out_size)
{
    const float* X    = (const float*)d_in[0];   // (4096,64,64)
    const float* W1   = (const float*)d_in[1];   // (64,128)
    const float* b1   = (const float*)d_in[2];
    const float* W2   = (const float*)d_in[3];   // (128,64)
    const float* b2   = (const float*)d_in[4];
    const float* W3   = (const float*)d_in[5];   // (64,32)
    const float* b3   = (const float*)d_in[6];
    const float* W4   = (const float*)d_in[7];   // (32,32)
    const float* b4   = (const float*)d_in[8];
    const float* P0   = (const float*)d_in[9];   // (64,64,32)
    const float* P1   = (const float*)d_in[10];  // (32,128,64)
    const float* P2   = (const float*)d_in[11];  // (16,256,128)
    const float* P3   = (const float*)d_in[12];  // (8,512,256)
    const float* P4   = (const float*)d_in[13];  // (4,512,512)
    const float* P5   = (const float*)d_in[14];  // (2,512,512)
    const float* Ptop = (const float*)d_in[15];  // (1000,512)
    float* out = (float*)d_out;                  // (4096,1000)

    float *h1, *bufA, *bufB;
    cudaGetSymbolAddress((void**)&h1,  g_h1);
    cudaGetSymbolAddress((void**)&bufA, g_bufA);
    cudaGetSymbolAddress((void**)&bufB, g_bufB);

    const dim3 blk(256);
    const int DYN_N = 2 * 3072 * 4;   // non-PROD: 24576 B
    const int DYN_P = 2 * 5120 * 4;   // PROD:     40960 B

    // MLP over 262144 rows
    mma_gemm<false, false, true><<<dim3(2048, 2, 1), blk, DYN_N>>>(
        X, 64, 0, 0, W1, 0, b1, h1, 128, 0, 128, 64);
    mma_gemm<false, false, true><<<dim3(2048, 1, 1), blk, DYN_N>>>(
        h1, 128, 0, 0, W2, 0, b2, bufA, 64, 0, 64, 128);
    mma_gemm<false, false, true><<<dim3(2048, 1, 1), blk, DYN_N>>>(
        bufA, 64, 0, 0, W3, 0, b3, h1, 32, 0, 32, 64);
    mma_gemm<false, false, false><<<dim3(2048, 1, 1), blk, DYN_N>>>(
        h1, 32, 0, 0, W4, 0, b4, bufB, 32, 0, 32, 32);

    // Leaf: t0[b,j,a] = sum_m P0[j,a,m] * F[b,j,m]   -> bufA (B,64,64)
    mma_gemm<false, true, false><<<dim3(32, 1, 64), blk, DYN_N>>>(
        bufB, 2048, 32, 0, P0, 2048, nullptr, bufA, 4096, 64, 64, 32);

    // Tree levels (pair-product fused into A fragment load)
    mma_gemm<true, true, false><<<dim3(32, 2, 32), blk, DYN_P>>>(
        bufA, 4096, 128, 64, P1, 128L * 64, nullptr, bufB, 4096, 128, 128, 64);
    mma_gemm<true, true, false><<<dim3(32, 4, 16), blk, DYN_P>>>(
        bufB, 4096, 256, 128, P2, 256L * 128, nullptr, bufA, 4096, 256, 256, 128);
    mma_gemm<true, true, false><<<dim3(32, 8, 8), blk, DYN_P>>>(
        bufA, 4096, 512, 256, P3, 512L * 256, nullptr, bufB, 4096, 512, 512, 256);
    mma_gemm<true, true, false><<<dim3(32, 8, 4), blk, DYN_P>>>(
        bufB, 4096, 1024, 512, P4, 512L * 512, nullptr, bufA, 2048, 512, 512, 512);
    mma_gemm<true, true, false><<<dim3(32, 8, 2), blk, DYN_P>>>(
        bufA, 2048, 1024, 512, P5, 512L * 512, nullptr, bufB, 1024, 512, 512, 512);

    // Top: out[b,y] = sum_a Ptop[y,a] * (t5[b,0,a]*t5[b,1,a])
    mma_gemm<true, true, false><<<dim3(32, 16, 1), blk, DYN_P>>>(
        bufB, 1024, 0, 512, Ptop, 0, nullptr, out, 1000, 0, 1000, 512);
}